// round 12
// baseline (speedup 1.0000x reference)
#include <cuda_runtime.h>
#include <cuda_bf16.h>

#define KEHALF_F 7.199822675975274f
#define MAX_ATOMS 500000
#define MAXZ 96
#define LOG2E_F 1.4426950408889634f

struct ZConsts {
    float spadiv;               // sp(adiv)
    float ns1, ns2, ns3, ns4;   // -sp(a_k) * log2(e)
    float c1n, c2n, c3n, c4n;   // KEHALF * sp(c_k)/csum
};

__device__ ZConsts g_consts;
__device__ float g_lut[MAXZ];            // k^sp(apow); 384B, L1-sticky
__device__ unsigned char g_zq[MAX_ATOMS];

// ---- cache-controlled load helpers -------------------------------------
// Streamed data: never allocate in L1 (protect the table's residency).
__device__ __forceinline__ float4 ld_stream_f4(const float4* p) {
    float4 v;
    asm volatile("ld.global.L1::no_allocate.v4.f32 {%0,%1,%2,%3}, [%4];"
                 : "=f"(v.x), "=f"(v.y), "=f"(v.z), "=f"(v.w) : "l"(p));
    return v;
}
__device__ __forceinline__ int4 ld_stream_i4(const int4* p) {
    int4 v;
    asm volatile("ld.global.L1::no_allocate.v4.b32 {%0,%1,%2,%3}, [%4];"
                 : "=r"(v.x), "=r"(v.y), "=r"(v.z), "=r"(v.w) : "l"(p));
    return v;
}
// Table gathers: sticky in L1.
__device__ __forceinline__ unsigned int ld_table_u8(const unsigned char* p) {
    unsigned int v;
    asm volatile("ld.global.L1::evict_last.u8 %0, [%1];" : "=r"(v) : "l"(p));
    return v;
}
__device__ __forceinline__ float ld_table_f32(const float* p) {
    float v;
    asm volatile("ld.global.L1::evict_last.f32 %0, [%1];" : "=f"(v) : "l"(p));
    return v;
}
// ------------------------------------------------------------------------

__device__ __forceinline__ float softplus_acc(float x) {
    return (x > 20.f) ? x : log1pf(expf(x));
}

// Quantize Zf to bytes, zero the output; block 0 also computes the scalar
// constants and the 96-entry z LUT.
__global__ void __launch_bounds__(256)
atom_kernel(const float* __restrict__ Zf, float* __restrict__ out, int n,
            const float* adiv, const float* apow,
            const float* c1, const float* c2, const float* c3, const float* c4,
            const float* a1, const float* a2, const float* a3, const float* a4) {
    int i = blockIdx.x * blockDim.x + threadIdx.x;
    if (i < n) {
        g_zq[i] = (unsigned char)__float2int_rn(Zf[i]);
        out[i] = 0.0f;
    }
    if (blockIdx.x == 0) {
        if (threadIdx.x < MAXZ) {
            float sp_apow = softplus_acc(*apow);
            g_lut[threadIdx.x] = powf((float)threadIdx.x, sp_apow);
        }
        if (threadIdx.x == 0) {
            ZConsts C;
            C.spadiv = softplus_acc(*adiv);
            C.ns1 = -softplus_acc(*a1) * LOG2E_F;
            C.ns2 = -softplus_acc(*a2) * LOG2E_F;
            C.ns3 = -softplus_acc(*a3) * LOG2E_F;
            C.ns4 = -softplus_acc(*a4) * LOG2E_F;
            float c1p = softplus_acc(*c1);
            float c2p = softplus_acc(*c2);
            float c3p = softplus_acc(*c3);
            float c4p = softplus_acc(*c4);
            float inv = KEHALF_F / (c1p + c2p + c3p + c4p);
            C.c1n = c1p * inv;
            C.c2n = c2p * inv;
            C.c3n = c3p * inv;
            C.c4n = c4p * inv;
            g_consts = C;
        }
    }
}

// 8 pairs/thread, all 16 byte-gathers batched for MLP. Zero smem (full L1D
// carveout hosts the table). Load order: indices -> gathers -> values, so the
// random-latency gathers issue earliest and the streams fill their shadow.
__global__ void __launch_bounds__(256)
pair_kernel(const float4* __restrict__ rij, const float4* __restrict__ cut,
            const int4* __restrict__ ii, const int4* __restrict__ jj,
            float* __restrict__ out, int noct) {
    int t = blockIdx.x * 256 + threadIdx.x;   // 8-pair group index
    if (t >= noct) return;
    ZConsts C = g_consts;

    // 1) index streams first
    int4 ia0 = ld_stream_i4(&ii[2 * t]);
    int4 ia1 = ld_stream_i4(&ii[2 * t + 1]);
    int4 ja0 = ld_stream_i4(&jj[2 * t]);
    int4 ja1 = ld_stream_i4(&jj[2 * t + 1]);

    int ia[8] = {ia0.x, ia0.y, ia0.z, ia0.w, ia1.x, ia1.y, ia1.z, ia1.w};
    int ja[8] = {ja0.x, ja0.y, ja0.z, ja0.w, ja1.x, ja1.y, ja1.z, ja1.w};

    // 2) all 16 random byte-gathers (sticky L1)
    unsigned int zi[8], zj[8];
#pragma unroll
    for (int k = 0; k < 8; k++) {
        zi[k] = ld_table_u8(&g_zq[ia[k]]);
        zj[k] = ld_table_u8(&g_zq[ja[k]]);
    }

    // 3) value streams overlap the gather latency
    float4 r0 = ld_stream_f4(&rij[2 * t]);
    float4 r1 = ld_stream_f4(&rij[2 * t + 1]);
    float4 v0 = ld_stream_f4(&cut[2 * t]);
    float4 v1 = ld_stream_f4(&cut[2 * t + 1]);

    float r[8]  = {r0.x, r0.y, r0.z, r0.w, r1.x, r1.y, r1.z, r1.w};
    float cv[8] = {v0.x, v0.y, v0.z, v0.w, v1.x, v1.y, v1.z, v1.w};

    // 4) LUT lookups (384B, L1-sticky)
    float zpi[8], zpj[8];
#pragma unroll
    for (int k = 0; k < 8; k++) {
        zpi[k] = ld_table_f32(&g_lut[zi[k]]);
        zpj[k] = ld_table_f32(&g_lut[zj[k]]);
    }

#pragma unroll
    for (int k = 0; k < 8; k++) {
        float ar = (zpi[k] + zpj[k]) * C.spadiv * r[k];
        float f = C.c1n * exp2f(C.ns1 * ar)
                + C.c2n * exp2f(C.ns2 * ar)
                + C.c3n * exp2f(C.ns3 * ar)
                + C.c4n * exp2f(C.ns4 * ar);
        float zz = (float)(int)(zi[k] * zj[k]);
        float contrib = __fdividef(f * cv[k] * zz, r[k]);
        atomicAdd(out + ia[k], contrib);   // unused return -> RED
    }
}

// Scalar tail (P % 8 != 0); not hit for P = 16M.
__global__ void pair_tail(const float* __restrict__ rij, const float* __restrict__ cut,
                          const int* __restrict__ ii, const int* __restrict__ jj,
                          float* __restrict__ out, int start, int P) {
    int p = start + blockIdx.x * blockDim.x + threadIdx.x;
    if (p >= P) return;
    ZConsts C = g_consts;
    unsigned int qi = g_zq[ii[p]];
    unsigned int qj = g_zq[jj[p]];
    float ar = (g_lut[qi] + g_lut[qj]) * C.spadiv * rij[p];
    float f = C.c1n * exp2f(C.ns1 * ar)
            + C.c2n * exp2f(C.ns2 * ar)
            + C.c3n * exp2f(C.ns3 * ar)
            + C.c4n * exp2f(C.ns4 * ar);
    float zz = (float)(int)(qi * qj);
    float contrib = __fdividef(f * cut[p] * zz, rij[p]);
    atomicAdd(out + ii[p], contrib);
}

extern "C" void kernel_launch(void* const* d_in, const int* in_sizes, int n_in,
                              void* d_out, int out_size) {
    // order: N, Zf, rij, cutoff_values, idx_i, idx_j,
    //        adiv, apow, c1, c2, c3, c4, a1, a2, a3, a4
    const float* Zf   = (const float*)d_in[1];
    const float* rij  = (const float*)d_in[2];
    const float* cutv = (const float*)d_in[3];
    const int*   ii   = (const int*)d_in[4];
    const int*   jj   = (const int*)d_in[5];
    const float* adiv = (const float*)d_in[6];
    const float* apow = (const float*)d_in[7];
    const float* c1   = (const float*)d_in[8];
    const float* c2   = (const float*)d_in[9];
    const float* c3   = (const float*)d_in[10];
    const float* c4   = (const float*)d_in[11];
    const float* a1   = (const float*)d_in[12];
    const float* a2   = (const float*)d_in[13];
    const float* a3   = (const float*)d_in[14];
    const float* a4   = (const float*)d_in[15];
    float* out = (float*)d_out;

    int n_atoms = in_sizes[1];
    int P       = in_sizes[2];
    if (n_atoms > MAX_ATOMS) n_atoms = MAX_ATOMS;

    atom_kernel<<<(n_atoms + 255) / 256, 256>>>(Zf, out, n_atoms,
                                                adiv, apow, c1, c2, c3, c4,
                                                a1, a2, a3, a4);

    int noct = P / 8;
    if (noct > 0) {
        pair_kernel<<<(noct + 255) / 256, 256>>>(
            (const float4*)rij, (const float4*)cutv,
            (const int4*)ii, (const int4*)jj, out, noct);
    }
    int done = noct * 8;
    int rem = P - done;
    if (rem > 0) {
        pair_tail<<<(rem + 255) / 256, 256>>>(rij, cutv, ii, jj, out, done, P);
    }
}

// round 16
// speedup vs baseline: 1.0024x; 1.0024x over previous
#include <cuda_runtime.h>
#include <cuda_bf16.h>

#define KEHALF_F 7.199822675975274f
#define MAX_ATOMS 500000
#define MAXZ 96
#define LOG2E_F 1.4426950408889634f

struct ZConsts {
    float spadiv;               // sp(adiv)
    float ns1, ns2, ns3, ns4;   // -sp(a_k) * log2(e)
    float c1n, c2n, c3n, c4n;   // KEHALF * sp(c_k)/csum
};

__device__ ZConsts g_consts;
__device__ float g_lut[MAXZ];            // k^sp(apow); 384B, ~broadcast in L1
__device__ unsigned char g_zq[MAX_ATOMS];

__device__ __forceinline__ float softplus_acc(float x) {
    return (x > 20.f) ? x : log1pf(expf(x));
}

// Vectorized: 4 atoms/thread. Quantize Zf to bytes, zero the output.
// Block 0 also computes the scalar constants and the 96-entry z LUT.
__global__ void __launch_bounds__(256)
atom_kernel(const float4* __restrict__ Zf4, float4* __restrict__ out4,
            int n4, int n,
            const float* __restrict__ Zf, float* __restrict__ out,
            const float* adiv, const float* apow,
            const float* c1, const float* c2, const float* c3, const float* c4,
            const float* a1, const float* a2, const float* a3, const float* a4) {
    int i = blockIdx.x * blockDim.x + threadIdx.x;
    if (i < n4) {
        float4 z4 = __ldcs(&Zf4[i]);
        uchar4 q;
        q.x = (unsigned char)__float2int_rn(z4.x);
        q.y = (unsigned char)__float2int_rn(z4.y);
        q.z = (unsigned char)__float2int_rn(z4.z);
        q.w = (unsigned char)__float2int_rn(z4.w);
        ((uchar4*)g_zq)[i] = q;
        out4[i] = make_float4(0.f, 0.f, 0.f, 0.f);
    }
    // scalar remainder atoms
    int rem_base = n4 * 4;
    int ri = rem_base + i;
    if (i < n - rem_base) {
        g_zq[ri] = (unsigned char)__float2int_rn(Zf[ri]);
        out[ri] = 0.0f;
    }
    if (blockIdx.x == 0) {
        if (threadIdx.x < MAXZ) {
            float sp_apow = softplus_acc(*apow);
            g_lut[threadIdx.x] = powf((float)threadIdx.x, sp_apow);
        }
        if (threadIdx.x == 0) {
            ZConsts C;
            C.spadiv = softplus_acc(*adiv);
            C.ns1 = -softplus_acc(*a1) * LOG2E_F;
            C.ns2 = -softplus_acc(*a2) * LOG2E_F;
            C.ns3 = -softplus_acc(*a3) * LOG2E_F;
            C.ns4 = -softplus_acc(*a4) * LOG2E_F;
            float c1p = softplus_acc(*c1);
            float c2p = softplus_acc(*c2);
            float c3p = softplus_acc(*c3);
            float c4p = softplus_acc(*c4);
            float inv = KEHALF_F / (c1p + c2p + c3p + c4p);
            C.c1n = c1p * inv;
            C.c2n = c2p * inv;
            C.c3n = c3p * inv;
            C.c4n = c4p * inv;
            g_consts = C;
        }
    }
}

// 16 pairs/thread: all 32 random byte-gathers issued up front (max per-warp
// MLP, still under the ~55 outstanding-LDG cap). Streams + LUT loaded lazily
// per 4-pair quad to bound register pressure. Zero smem: full 228KB L1D
// carveout hosts the 500KB byte table.
__global__ void __launch_bounds__(256)
pair_kernel(const float4* __restrict__ rij, const float4* __restrict__ cut,
            const int4* __restrict__ ii, const int4* __restrict__ jj,
            float* __restrict__ out, int ngrp) {
    int t = blockIdx.x * 256 + threadIdx.x;   // 16-pair group index
    if (t >= ngrp) return;
    ZConsts C = g_consts;

    // 1) all index quads
    int ia[16], ja[16];
#pragma unroll
    for (int q = 0; q < 4; q++) {
        int4 iv = __ldcs(&ii[4 * t + q]);
        int4 jv = __ldcs(&jj[4 * t + q]);
        ia[4 * q + 0] = iv.x; ia[4 * q + 1] = iv.y;
        ia[4 * q + 2] = iv.z; ia[4 * q + 3] = iv.w;
        ja[4 * q + 0] = jv.x; ja[4 * q + 1] = jv.y;
        ja[4 * q + 2] = jv.z; ja[4 * q + 3] = jv.w;
    }

    // 2) all 32 random byte-gathers in flight
    unsigned int zi[16], zj[16];
#pragma unroll
    for (int k = 0; k < 16; k++) {
        zi[k] = __ldg(&g_zq[ia[k]]);
        zj[k] = __ldg(&g_zq[ja[k]]);
    }

    // 3) per-quad: stream values, LUT, compute, RED
#pragma unroll
    for (int q = 0; q < 4; q++) {
        float4 r4 = __ldcs(&rij[4 * t + q]);
        float4 v4 = __ldcs(&cut[4 * t + q]);
        float r[4]  = {r4.x, r4.y, r4.z, r4.w};
        float cv[4] = {v4.x, v4.y, v4.z, v4.w};
#pragma unroll
        for (int m = 0; m < 4; m++) {
            int k = 4 * q + m;
            float zpi = __ldg(&g_lut[zi[k]]);
            float zpj = __ldg(&g_lut[zj[k]]);
            float ar = (zpi + zpj) * C.spadiv * r[m];
            float f = C.c1n * exp2f(C.ns1 * ar)
                    + C.c2n * exp2f(C.ns2 * ar)
                    + C.c3n * exp2f(C.ns3 * ar)
                    + C.c4n * exp2f(C.ns4 * ar);
            float zz = (float)(int)(zi[k] * zj[k]);
            float contrib = __fdividef(f * cv[m] * zz, r[m]);
            atomicAdd(out + ia[k], contrib);   // unused return -> RED
        }
    }
}

// Scalar tail (P % 16 != 0); not hit for P = 16M.
__global__ void pair_tail(const float* __restrict__ rij, const float* __restrict__ cut,
                          const int* __restrict__ ii, const int* __restrict__ jj,
                          float* __restrict__ out, int start, int P) {
    int p = start + blockIdx.x * blockDim.x + threadIdx.x;
    if (p >= P) return;
    ZConsts C = g_consts;
    unsigned int qi = g_zq[ii[p]];
    unsigned int qj = g_zq[jj[p]];
    float ar = (g_lut[qi] + g_lut[qj]) * C.spadiv * rij[p];
    float f = C.c1n * exp2f(C.ns1 * ar)
            + C.c2n * exp2f(C.ns2 * ar)
            + C.c3n * exp2f(C.ns3 * ar)
            + C.c4n * exp2f(C.ns4 * ar);
    float zz = (float)(int)(qi * qj);
    float contrib = __fdividef(f * cut[p] * zz, rij[p]);
    atomicAdd(out + ii[p], contrib);
}

extern "C" void kernel_launch(void* const* d_in, const int* in_sizes, int n_in,
                              void* d_out, int out_size) {
    // order: N, Zf, rij, cutoff_values, idx_i, idx_j,
    //        adiv, apow, c1, c2, c3, c4, a1, a2, a3, a4
    const float* Zf   = (const float*)d_in[1];
    const float* rij  = (const float*)d_in[2];
    const float* cutv = (const float*)d_in[3];
    const int*   ii   = (const int*)d_in[4];
    const int*   jj   = (const int*)d_in[5];
    const float* adiv = (const float*)d_in[6];
    const float* apow = (const float*)d_in[7];
    const float* c1   = (const float*)d_in[8];
    const float* c2   = (const float*)d_in[9];
    const float* c3   = (const float*)d_in[10];
    const float* c4   = (const float*)d_in[11];
    const float* a1   = (const float*)d_in[12];
    const float* a2   = (const float*)d_in[13];
    const float* a3   = (const float*)d_in[14];
    const float* a4   = (const float*)d_in[15];
    float* out = (float*)d_out;

    int n_atoms = in_sizes[1];
    int P       = in_sizes[2];
    if (n_atoms > MAX_ATOMS) n_atoms = MAX_ATOMS;

    int n4 = n_atoms / 4;
    int ablocks = (n4 + 255) / 256;
    if (ablocks < 1) ablocks = 1;
    atom_kernel<<<ablocks, 256>>>((const float4*)Zf, (float4*)out, n4, n_atoms,
                                  Zf, out,
                                  adiv, apow, c1, c2, c3, c4,
                                  a1, a2, a3, a4);

    int ngrp = P / 16;
    if (ngrp > 0) {
        pair_kernel<<<(ngrp + 255) / 256, 256>>>(
            (const float4*)rij, (const float4*)cutv,
            (const int4*)ii, (const int4*)jj, out, ngrp);
    }
    int done = ngrp * 16;
    int rem = P - done;
    if (rem > 0) {
        pair_tail<<<(rem + 255) / 256, 256>>>(rij, cutv, ii, jj, out, done, P);
    }
}